// round 10
// baseline (speedup 1.0000x reference)
#include <cuda_runtime.h>
#include <cstdint>
#include <math.h>

#define DIM 128
#define FFN 512
#define KNN 9
#define TPB 256
#define RT  128      // rows per CTA tile
#define KPH 32       // k-depth per phase
#define NXQ 8        // k-quads per phase
#define NMAX 50000

// Xd blocked-linear layout: float offset = (k>>2)*XB + (k&3)*XJ + 4*pair
// pair p holds dup(row 2p) | dup(row 2p+1) in 16B. XB==20 mod 32 banks.
#define XB 1044
#define XJ 260
#define WS_FLOATS (KPH * 128)    // 4096
#define XD_FLOATS (NXQ * XB)     // 8352

typedef unsigned long long ull;

// ---- packed f32x2 helpers ----
__device__ __forceinline__ ull ffma2(ull a, ull b, ull c) {
    ull d;
    asm("fma.rn.f32x2 %0, %1, %2, %3;" : "=l"(d) : "l"(a), "l"(b), "l"(c));
    return d;
}
__device__ __forceinline__ ull add2(ull a, ull b) {
    ull d;
    asm("add.rn.f32x2 %0, %1, %2;" : "=l"(d) : "l"(a), "l"(b));
    return d;
}
__device__ __forceinline__ ull dup2(float v) {
    unsigned u = __float_as_uint(v);
    ull r;
    asm("mov.b64 %0, {%1, %1};" : "=l"(r) : "r"(u));
    return r;
}
__device__ __forceinline__ float lo2(ull a) {
    unsigned l, h;
    asm("mov.b64 {%0, %1}, %2;" : "=r"(l), "=r"(h) : "l"(a));
    return __uint_as_float(l);
}
__device__ __forceinline__ float hi2(ull a) {
    unsigned l, h;
    asm("mov.b64 {%0, %1}, %2;" : "=r"(l), "=r"(h) : "l"(a));
    return __uint_as_float(h);
}
__device__ __forceinline__ float gelu_exact(float v) {
    return 0.5f * v * (1.0f + erff(v * 0.70710678118654752f));
}

// ---- scratch (static device globals; no allocations anywhere) ----
__device__ float g_h [(size_t)NMAX * DIM];
__device__ float g_h2[(size_t)NMAX * DIM];
__device__ float g_x1[(size_t)NMAX * DIM];
__device__ float g_t [(size_t)NMAX * FFN];

// =====================================================================
// Split staging: gmem->regs (issue early) and regs->smem (commit late)
// =====================================================================
// Weights: Ws[k][.] 128 cols, quads interleaved: dest quad = (q&1)*16+(q>>1)
__device__ __forceinline__ void w_load(float4 wv[4], const float* __restrict__ W,
        int krow0, int ldw, int colbase, int tid) {
    #pragma unroll
    for (int p = 0; p < 4; p++) {
        int i = tid + p * TPB;            // 1024 float4s
        int k = i >> 5, q = i & 31;
        wv[p] = *(const float4*)(W + (size_t)(krow0 + k) * ldw + colbase + q * 4);
    }
}
__device__ __forceinline__ void w_store(float* Ws, const float4 wv[4], int tid) {
    #pragma unroll
    for (int p = 0; p < 4; p++) {
        int i = tid + p * TPB;
        int k = i >> 5, q = i & 31;
        int dq = ((q & 1) << 4) + (q >> 1);
        *(float4*)(Ws + k * 128 + dq * 4) = wv[p];
    }
}

// x: thread = (k-quad m = tid&7, pair base pb = tid>>3), 2 pair-tasks.
// Each LDG.128 warp-instr reads 4 rows x 128B contiguous (aligned) = 4 lines.
__device__ __forceinline__ void x_load(float4 xa[2], float4 xb[2],
        const float* __restrict__ src, int lds, int k0, int row0, int n, int tid) {
    const int m = tid & 7, pb = tid >> 3;
    #pragma unroll
    for (int it = 0; it < 2; it++) {
        int p = pb + 32 * it;
        int rowA = row0 + 2 * p, rowB = rowA + 1;
        xa[it] = (rowA < n) ? *(const float4*)(src + (size_t)rowA * lds + k0 + 4 * m)
                            : make_float4(0.f, 0.f, 0.f, 0.f);
        xb[it] = (rowB < n) ? *(const float4*)(src + (size_t)rowB * lds + k0 + 4 * m)
                            : make_float4(0.f, 0.f, 0.f, 0.f);
    }
}
__device__ __forceinline__ void x_store(float* Xd, const float4 xa[2],
        const float4 xb[2], int tid) {
    const int m = tid & 7, pb = tid >> 3;
    #pragma unroll
    for (int it = 0; it < 2; it++) {
        int p = pb + 32 * it;
        float* xb_ = Xd + m * XB + 4 * p;
        ulonglong2 t;
        t.x = dup2(xa[it].x); t.y = dup2(xb[it].x); *(ulonglong2*)(xb_         ) = t;
        t.x = dup2(xa[it].y); t.y = dup2(xb[it].y); *(ulonglong2*)(xb_ + XJ    ) = t;
        t.x = dup2(xa[it].z); t.y = dup2(xb[it].z); *(ulonglong2*)(xb_ + 2 * XJ) = t;
        t.x = dup2(xa[it].w); t.y = dup2(xb[it].w); *(ulonglong2*)(xb_ + 3 * XJ) = t;
    }
}

// =====================================================================
// 8x8 register-tile MMA over one 32-deep k-phase.
// Per k: 2 weight LDS.128 + 4 x LDS.128 (broadcast-pair) + 32 FFMA2.
// =====================================================================
__device__ __forceinline__ void mma_phase(const float* Ws, const float* Xd,
        int cg, int rg, ull acc[8][4]) {
    const float* wp = Ws + cg * 4;
    const float* xp = Xd + rg * 16;
    #pragma unroll 4
    for (int m = 0; m < NXQ; m++) {
        const float* wk = wp + m * 512;
        const float* xk = xp + m * XB;
        #pragma unroll
        for (int j = 0; j < 4; j++) {
            ulonglong2 wA = *(const ulonglong2*)(wk + j * 128);
            ulonglong2 wB = *(const ulonglong2*)(wk + j * 128 + 64);
            const float* xj = xk + j * XJ;
            ulonglong2 x0 = *(const ulonglong2*)(xj);
            ulonglong2 x1 = *(const ulonglong2*)(xj + 4);
            ulonglong2 x2 = *(const ulonglong2*)(xj + 8);
            ulonglong2 x3 = *(const ulonglong2*)(xj + 12);
            #define ROWF(i, xv)                                                 \
                acc[i][0] = ffma2(xv, wA.x, acc[i][0]);                         \
                acc[i][1] = ffma2(xv, wA.y, acc[i][1]);                         \
                acc[i][2] = ffma2(xv, wB.x, acc[i][2]);                         \
                acc[i][3] = ffma2(xv, wB.y, acc[i][3]);
            ROWF(0, x0.x) ROWF(1, x0.y) ROWF(2, x1.x) ROWF(3, x1.y)
            ROWF(4, x2.x) ROWF(5, x2.y) ROWF(6, x3.x) ROWF(7, x3.y)
            #undef ROWF
        }
    }
}

__device__ __forceinline__ void acc_init(ull acc[8][4], const float* __restrict__ bp) {
    ull b0 = *(const ull*)(bp), b1 = *(const ull*)(bp + 2);
    ull b2 = *(const ull*)(bp + 4), b3 = *(const ull*)(bp + 6);
    #pragma unroll
    for (int r = 0; r < 8; r++) {
        acc[r][0] = b0; acc[r][1] = b1; acc[r][2] = b2; acc[r][3] = b3;
    }
}

// =====================================================================
// Double-buffered pipelined GEMM mainloop (nph even, >= 2).
// Phase ph data lives in buffer (ph&1). NOTE: returns WITHOUT trailing sync.
// =====================================================================
__device__ __forceinline__ void gemm_pipe(float* sm,
        const float* __restrict__ src, int lds,
        const float* __restrict__ W, int ldw, int colbase,
        int nph, int row0, int n, int tid, int cg, int rg, ull acc[8][4]) {
    float* Ws0 = sm;
    float* Ws1 = sm + WS_FLOATS;
    float* Xd0 = sm + 2 * WS_FLOATS;
    float* Xd1 = Xd0 + XD_FLOATS;
    float4 wv[4], xa[2], xb[2];
    w_load(wv, W, 0, ldw, colbase, tid);
    x_load(xa, xb, src, lds, 0, row0, n, tid);
    w_store(Ws0, wv, tid);
    x_store(Xd0, xa, xb, tid);
    __syncthreads();
    #pragma unroll 1
    for (int ph = 0; ph < nph; ph += 2) {
        // even phase: compute buf0, stage ph+1 into buf1
        w_load(wv, W, (ph + 1) * KPH, ldw, colbase, tid);
        x_load(xa, xb, src, lds, (ph + 1) * KPH, row0, n, tid);
        mma_phase(Ws0, Xd0, cg, rg, acc);
        w_store(Ws1, wv, tid);
        x_store(Xd1, xa, xb, tid);
        __syncthreads();
        // odd phase: compute buf1, stage ph+2 into buf0
        if (ph + 2 < nph) {
            w_load(wv, W, (ph + 2) * KPH, ldw, colbase, tid);
            x_load(xa, xb, src, lds, (ph + 2) * KPH, row0, n, tid);
        }
        mma_phase(Ws1, Xd1, cg, rg, acc);
        if (ph + 2 < nph) {
            w_store(Ws0, wv, tid);
            x_store(Xd0, xa, xb, tid);
            __syncthreads();
        }
    }
}

// acc[r] holds one row's 8 columns as 4 packed (lo,hi)=adjacent-column pairs.
__device__ __forceinline__ void store_rows(float* __restrict__ dst, int dstride,
        ull acc[8][4], int row0, int n, int cg, int rg) {
    const int c = cg * 8;
    #pragma unroll
    for (int r = 0; r < 8; r++) {
        int row = row0 + rg * 8 + r;
        if (row < n) {
            ulonglong2 p0, p1;
            p0.x = acc[r][0]; p0.y = acc[r][1];
            p1.x = acc[r][2]; p1.y = acc[r][3];
            *(ulonglong2*)(dst + (size_t)row * dstride + c) = p0;
            *(ulonglong2*)(dst + (size_t)row * dstride + c + 4) = p1;
        }
    }
}

__device__ __forceinline__ void resid_store(float* resid, ull acc[8][4],
        const float* __restrict__ xres, int row0, int n, int cg, int rg) {
    const int c = cg * 8;
    #pragma unroll
    for (int r = 0; r < 8; r++) {
        int rl = rg * 8 + r;
        int row = row0 + rl;
        if (row < n) {
            ulonglong2 x0 = *(const ulonglong2*)(xres + (size_t)row * DIM + c);
            ulonglong2 x1 = *(const ulonglong2*)(xres + (size_t)row * DIM + c + 4);
            ulonglong2 p0, p1;
            p0.x = add2(acc[r][0], x0.x); p0.y = add2(acc[r][1], x0.y);
            p1.x = add2(acc[r][2], x1.x); p1.y = add2(acc[r][3], x1.y);
            *(ulonglong2*)(resid + rl * DIM + c) = p0;
            *(ulonglong2*)(resid + rl * DIM + c + 4) = p1;
        }
    }
}

__device__ __forceinline__ void ln_rows(const float* resid,
        const float* __restrict__ gam, const float* __restrict__ bet,
        float* __restrict__ dst, int dstride, int row0, int n, int tid) {
    const int wid = tid >> 5, lane = tid & 31;
    const int d = lane * 4;
    float4 gv = *(const float4*)(gam + d);
    float4 bv = *(const float4*)(bet + d);
    for (int rl = wid; rl < RT; rl += 8) {
        int row = row0 + rl;
        if (row >= n) continue;
        float4 v = *(const float4*)(resid + rl * DIM + d);
        float s  = v.x + v.y + v.z + v.w;
        float sq = v.x * v.x + v.y * v.y + v.z * v.z + v.w * v.w;
        #pragma unroll
        for (int m = 16; m; m >>= 1) {
            s  += __shfl_xor_sync(0xffffffffu, s,  m);
            sq += __shfl_xor_sync(0xffffffffu, sq, m);
        }
        float mu = s * (1.f / DIM);
        float var = sq * (1.f / DIM) - mu * mu;
        float rs = rsqrtf(var + 1e-5f);
        float4 o;
        o.x = (v.x - mu) * rs * gv.x + bv.x;
        o.y = (v.y - mu) * rs * gv.y + bv.y;
        o.z = (v.z - mu) * rs * gv.z + bv.z;
        o.w = (v.w - mu) * rs * gv.w + bv.w;
        *(float4*)(dst + (size_t)row * dstride + d) = o;
    }
}

// =====================================================================
// Kernel A: h = x @ W_in + b
// =====================================================================
__global__ __launch_bounds__(TPB, 2) void k_win(const float* __restrict__ x,
        const float* __restrict__ W, const float* __restrict__ b, int n) {
    extern __shared__ float sm[];
    const int tid = threadIdx.x;
    const int cg = tid & 15, rg = tid >> 4;
    const int row0 = blockIdx.x * RT;
    ull acc[8][4];
    acc_init(acc, b + cg * 8);
    gemm_pipe(sm, x, DIM, W, DIM, 0, 4, row0, n, tid, cg, rg, acc);
    store_rows(g_h, DIM, acc, row0, n, cg, rg);
}

// =====================================================================
// Kernel B1: h2 = [h | maxdiff] @ W_upd + bu.  K=256 in 8 phases of 32:
// 4 plain (from g_h) + 4 gather phases.  Loads issued pre-sync so they
// overlap the previous phase's MMA. edge_index dtype auto-detected.
// =====================================================================
__global__ __launch_bounds__(TPB, 2) void k_msg1(const void* __restrict__ eidx,
        const float* __restrict__ Wu, const float* __restrict__ bu, int n) {
    extern __shared__ float sm[];
    float* Ws = sm;
    float* Xd = sm + WS_FLOATS;
    int* srcb = (int*)(Xd + XD_FLOATS);      // RT*KNN
    int* flag = srcb + RT * KNN;
    const int tid = threadIdx.x;
    const int cg = tid & 15, rg = tid >> 4;
    const int row0 = blockIdx.x * RT;
    if (tid == 0) {
        const long long* p64 = (const long long*)eidx;
        int ok = 1;
        #pragma unroll
        for (int i = 0; i < 16; i++) {
            long long v = p64[i];
            if (v < 0 || v >= (long long)n) ok = 0;
        }
        *flag = ok;
    }
    __syncthreads();
    const int is64 = *flag;
    for (int i = tid; i < RT * KNN; i += TPB) {
        int r = i / KNN;
        int row = row0 + r;
        int s = 0;
        if (row < n) {
            size_t e = (size_t)row * KNN + (i - r * KNN);
            long long v = is64 ? ((const long long*)eidx)[e]
                               : (long long)((const int*)eidx)[e];
            s = (int)v;
            s = min(max(s, 0), n - 1);
        }
        srcb[i] = s;
    }
    ull acc[8][4];
    acc_init(acc, bu + cg * 8);
    // 4 plain phases (h half)
    #pragma unroll 1
    for (int gph = 0; gph < 4; gph++) {
        float4 wv[4], xa[2], xb[2];
        w_load(wv, Wu, gph * KPH, DIM, 0, tid);
        x_load(xa, xb, g_h, DIM, gph * KPH, row0, n, tid);
        __syncthreads();          // prev phase MMA done (also covers srcb fill)
        w_store(Ws, wv, tid);
        x_store(Xd, xa, xb, tid);
        __syncthreads();
        mma_phase(Ws, Xd, cg, rg, acc);
    }
    // 4 gather phases (maxdiff half)
    #pragma unroll 1
    for (int gph = 0; gph < 4; gph++) {
        float4 wv[4], oA[2], oB[2];
        w_load(wv, Wu, DIM + gph * KPH, DIM, 0, tid);
        {
            const int m = tid & 7, pb = tid >> 3;
            const int d0 = gph * KPH + 4 * m;
            #pragma unroll
            for (int it = 0; it < 2; it++) {
                int p = pb + 32 * it;
                int rA = 2 * p, rB = rA + 1;
                int rowA = row0 + rA, rowB = row0 + rB;
                const int* sA = srcb + rA * KNN;
                const int* sB = srcb + rB * KNN;
                float4 mA = make_float4(-3.4e38f, -3.4e38f, -3.4e38f, -3.4e38f);
                float4 mB = mA;
                #pragma unroll
                for (int j = 0; j < KNN; j++) {
                    float4 g = *(const float4*)(g_h + (size_t)sA[j] * DIM + d0);
                    mA.x = fmaxf(mA.x, g.x); mA.y = fmaxf(mA.y, g.y);
                    mA.z = fmaxf(mA.z, g.z); mA.w = fmaxf(mA.w, g.w);
                }
                #pragma unroll
                for (int j = 0; j < KNN; j++) {
                    float4 g = *(const float4*)(g_h + (size_t)sB[j] * DIM + d0);
                    mB.x = fmaxf(mB.x, g.x); mB.y = fmaxf(mB.y, g.y);
                    mB.z = fmaxf(mB.z, g.z); mB.w = fmaxf(mB.w, g.w);
                }
                oA[it] = make_float4(0.f, 0.f, 0.f, 0.f);
                oB[it] = oA[it];
                if (rowA < n) {
                    float4 a = *(const float4*)(g_h + (size_t)rowA * DIM + d0);
                    oA[it] = make_float4(mA.x - a.x, mA.y - a.y, mA.z - a.z, mA.w - a.w);
                }
                if (rowB < n) {
                    float4 a = *(const float4*)(g_h + (size_t)rowB * DIM + d0);
                    oB[it] = make_float4(mB.x - a.x, mB.y - a.y, mB.z - a.z, mB.w - a.w);
                }
            }
        }
        __syncthreads();
        w_store(Ws, wv, tid);
        x_store(Xd, oA, oB, tid);
        __syncthreads();
        mma_phase(Ws, Xd, cg, rg, acc);
    }
    store_rows(g_h2, DIM, acc, row0, n, cg, rg);
}

// =====================================================================
// Kernel B2: h3 = h2 @ W_out + bo; x1 = LN1(x + h3) -> g_x1
// =====================================================================
__global__ __launch_bounds__(TPB, 2) void k_msg2(const float* __restrict__ x,
        const float* __restrict__ Wo, const float* __restrict__ bo,
        const float* __restrict__ g1, const float* __restrict__ b1, int n) {
    extern __shared__ float sm[];
    const int tid = threadIdx.x;
    const int cg = tid & 15, rg = tid >> 4;
    const int row0 = blockIdx.x * RT;
    ull acc[8][4];
    acc_init(acc, bo + cg * 8);
    gemm_pipe(sm, g_h2, DIM, Wo, DIM, 0, 4, row0, n, tid, cg, rg, acc);
    __syncthreads();            // all MMA reads done; reuse smem as resid
    float* resid = sm;          // RT*DIM = 64KB < 97KB
    resid_store(resid, acc, x, row0, n, cg, rg);
    __syncthreads();
    ln_rows(resid, g1, b1, g_x1, DIM, row0, n, tid);
}

// =====================================================================
// Kernel C: t = gelu(x1 @ ffn1 + b)   (grid.y = 4 col-slices of 128)
// =====================================================================
__global__ __launch_bounds__(TPB, 2) void k_ffn1(const float* __restrict__ W,
        const float* __restrict__ b, int n) {
    extern __shared__ float sm[];
    const int tid = threadIdx.x;
    const int cg = tid & 15, rg = tid >> 4;
    const int row0 = blockIdx.x * RT;
    const int colbase = blockIdx.y * 128;
    const int c = cg * 8;
    ull acc[8][4];
    acc_init(acc, b + colbase + c);
    gemm_pipe(sm, g_x1, DIM, W, FFN, colbase, 4, row0, n, tid, cg, rg, acc);
    #pragma unroll
    for (int r = 0; r < 8; r++) {
        int row = row0 + rg * 8 + r;
        if (row < n) {
            float4 f0, f1;
            f0.x = gelu_exact(lo2(acc[r][0])); f0.y = gelu_exact(hi2(acc[r][0]));
            f0.z = gelu_exact(lo2(acc[r][1])); f0.w = gelu_exact(hi2(acc[r][1]));
            f1.x = gelu_exact(lo2(acc[r][2])); f1.y = gelu_exact(hi2(acc[r][2]));
            f1.z = gelu_exact(lo2(acc[r][3])); f1.w = gelu_exact(hi2(acc[r][3]));
            *(float4*)(g_t + (size_t)row * FFN + colbase + c) = f0;
            *(float4*)(g_t + (size_t)row * FFN + colbase + c + 4) = f1;
        }
    }
}

// =====================================================================
// Kernel D: f = t @ ffn2 + b2; out = LN2(x1 + f)   (K=512, 16 phases)
// =====================================================================
__global__ __launch_bounds__(TPB, 2) void k_ffn2(const float* __restrict__ W,
        const float* __restrict__ b2, const float* __restrict__ g2,
        const float* __restrict__ bl, float* __restrict__ out, int n) {
    extern __shared__ float sm[];
    const int tid = threadIdx.x;
    const int cg = tid & 15, rg = tid >> 4;
    const int row0 = blockIdx.x * RT;
    ull acc[8][4];
    acc_init(acc, b2 + cg * 8);
    gemm_pipe(sm, g_t, FFN, W, DIM, 0, 16, row0, n, tid, cg, rg, acc);
    __syncthreads();            // reuse smem as resid
    float* resid = sm;
    resid_store(resid, acc, g_x1, row0, n, cg, rg);
    __syncthreads();
    ln_rows(resid, g2, bl, out, DIM, row0, n, tid);
}

// =====================================================================
extern "C" void kernel_launch(void* const* d_in, const int* in_sizes, int n_in,
                              void* d_out, int out_size) {
    const float* x    = (const float*)d_in[0];
    const void*  ei   = (const void*)d_in[1];   // edge_index [2,E]; row 0 = src
    const float* Winw = (const float*)d_in[2];
    const float* Winb = (const float*)d_in[3];
    const float* Wupw = (const float*)d_in[4];
    const float* Wupb = (const float*)d_in[5];
    const float* Wouw = (const float*)d_in[6];
    const float* Woub = (const float*)d_in[7];
    const float* ln1g = (const float*)d_in[8];
    const float* ln1b = (const float*)d_in[9];
    const float* ln2g = (const float*)d_in[10];
    const float* ln2b = (const float*)d_in[11];
    const float* f1w  = (const float*)d_in[12];
    const float* f1b  = (const float*)d_in[13];
    const float* f2w  = (const float*)d_in[14];
    const float* f2b  = (const float*)d_in[15];
    float* out = (float*)d_out;

    const int n = in_sizes[0] / DIM;

    const int SMEM_PIPE = (2 * WS_FLOATS + 2 * XD_FLOATS) * 4;   // 99584 B
    const int SMEM_MSG1 = (WS_FLOATS + XD_FLOATS) * 4 + (RT * KNN + 1) * 4;

    cudaFuncSetAttribute(k_win,  cudaFuncAttributeMaxDynamicSharedMemorySize, SMEM_PIPE);
    cudaFuncSetAttribute(k_msg1, cudaFuncAttributeMaxDynamicSharedMemorySize, SMEM_MSG1);
    cudaFuncSetAttribute(k_msg2, cudaFuncAttributeMaxDynamicSharedMemorySize, SMEM_PIPE);
    cudaFuncSetAttribute(k_ffn1, cudaFuncAttributeMaxDynamicSharedMemorySize, SMEM_PIPE);
    cudaFuncSetAttribute(k_ffn2, cudaFuncAttributeMaxDynamicSharedMemorySize, SMEM_PIPE);

    const int nb = (n + RT - 1) / RT;
    dim3 gc(nb, 4);

    k_win <<<nb, TPB, SMEM_PIPE>>>(x, Winw, Winb, n);
    k_msg1<<<nb, TPB, SMEM_MSG1>>>(ei, Wupw, Wupb, n);
    k_msg2<<<nb, TPB, SMEM_PIPE>>>(x, Wouw, Woub, ln1g, ln1b, n);
    k_ffn1<<<gc, TPB, SMEM_PIPE>>>(f1w, f1b, n);
    k_ffn2<<<nb, TPB, SMEM_PIPE>>>(f2w, f2b, ln2g, ln2b, out, n);
}

// round 12
// speedup vs baseline: 1.3311x; 1.3311x over previous
#include <cuda_runtime.h>
#include <cuda_bf16.h>
#include <cstdint>
#include <math.h>

#define DIM 128
#define FFN 512
#define KNN 9
#define TPB 256
#define RT  128      // rows per CTA tile
#define KPH 64       // k-depth per phase (fp32 path)
#define NMAX 50000

// fp32-path Xd blocked-linear layout (round-9, proven):
#define XB 1044
#define XJ 260
#define XD_FLOATS (16 * XB)

// bf16 MMA smem tile stride (elements): 128 + 8 pad -> conflict-free ldmatrix
#define SA 136
#define RSTR 132     // ffn2 resid smem row stride (floats)

typedef unsigned long long ull;

// ====================== packed f32x2 helpers (fp32 path) ==================
__device__ __forceinline__ ull ffma2(ull a, ull b, ull c) {
    ull d;
    asm("fma.rn.f32x2 %0, %1, %2, %3;" : "=l"(d) : "l"(a), "l"(b), "l"(c));
    return d;
}
__device__ __forceinline__ ull add2(ull a, ull b) {
    ull d;
    asm("add.rn.f32x2 %0, %1, %2;" : "=l"(d) : "l"(a), "l"(b));
    return d;
}
__device__ __forceinline__ ull dup2(float v) {
    unsigned u = __float_as_uint(v);
    ull r;
    asm("mov.b64 %0, {%1, %1};" : "=l"(r) : "r"(u));
    return r;
}
__device__ __forceinline__ float gelu_exact(float v) {
    return 0.5f * v * (1.0f + erff(v * 0.70710678118654752f));
}
__device__ __forceinline__ uint32_t pbf(float a, float b) {
    uint16_t ua = __bfloat16_as_ushort(__float2bfloat16(a));
    uint16_t ub = __bfloat16_as_ushort(__float2bfloat16(b));
    return (uint32_t)ua | ((uint32_t)ub << 16);
}
__device__ __forceinline__ float bf_hi(float v) {
    return __bfloat162float(__float2bfloat16(v));
}

// ====================== HMMA (compute_100-safe) helpers ===================
__device__ __forceinline__ uint32_t s2u(const void* p) {
    uint32_t a;
    asm("{ .reg .u64 t; cvta.to.shared.u64 t, %1; cvt.u32.u64 %0, t; }"
        : "=r"(a) : "l"(p));
    return a;
}
__device__ __forceinline__ void ldsm4(uint32_t* r, uint32_t addr) {
    asm volatile("ldmatrix.sync.aligned.m8n8.x4.shared.b16 {%0,%1,%2,%3}, [%4];"
        : "=r"(r[0]), "=r"(r[1]), "=r"(r[2]), "=r"(r[3]) : "r"(addr));
}
__device__ __forceinline__ void mma_bf16(float* c, const uint32_t* a,
                                         uint32_t b0, uint32_t b1) {
    asm volatile(
        "mma.sync.aligned.m16n8k16.row.col.f32.bf16.bf16.f32 "
        "{%0,%1,%2,%3}, {%4,%5,%6,%7}, {%8,%9}, {%0,%1,%2,%3};"
        : "+f"(c[0]), "+f"(c[1]), "+f"(c[2]), "+f"(c[3])
        : "r"(a[0]), "r"(a[1]), "r"(a[2]), "r"(a[3]), "r"(b0), "r"(b1));
}

// ====================== scratch (no allocations anywhere) =================
__device__ float g_h [(size_t)NMAX * DIM];
__device__ float g_h2[(size_t)NMAX * DIM];
__device__ float g_x1[(size_t)NMAX * DIM];
__device__ __align__(256) __nv_bfloat16 g_x1h[(size_t)NMAX * DIM];
__device__ __align__(256) __nv_bfloat16 g_x1l[(size_t)NMAX * DIM];
__device__ __align__(256) __nv_bfloat16 g_th [(size_t)NMAX * FFN];
__device__ __align__(256) __nv_bfloat16 g_tl [(size_t)NMAX * FFN];
__device__ __align__(256) __nv_bfloat16 g_w1h[FFN * DIM], g_w1l[FFN * DIM]; // [n=512,k=128]
__device__ __align__(256) __nv_bfloat16 g_w2h[DIM * FFN], g_w2l[DIM * FFN]; // [n=128,k=512]

// ====================== fp32 FFMA2 path (round 9, proven) =================
__device__ __forceinline__ void stage_w(float* Ws, const float* __restrict__ W,
        int krow0, int ldw, int colbase, int tid) {
    #pragma unroll
    for (int p = 0; p < 8; p++) {
        int i = tid + p * TPB;
        int k = i >> 5, q = i & 31;
        int dq = ((q & 1) << 4) + (q >> 1);
        *(float4*)(Ws + k * 128 + dq * 4) =
            *(const float4*)(W + (size_t)(krow0 + k) * ldw + colbase + q * 4);
    }
}
__device__ __forceinline__ void stage_x(float* Xd, const float* __restrict__ src,
        int lds, int k0, int row0, int n, int tid) {
    const int m  = tid & 15;
    const int rp = (tid >> 4) & 1;
    const int w  = tid >> 5;
    #pragma unroll
    for (int it = 0; it < 4; it++) {
        int p = (((w << 2) + it) << 1) + rp;
        int rowA = row0 + 2 * p, rowB = rowA + 1;
        float4 a = make_float4(0.f, 0.f, 0.f, 0.f), b = a;
        if (rowA < n) a = *(const float4*)(src + (size_t)rowA * lds + k0 + 4 * m);
        if (rowB < n) b = *(const float4*)(src + (size_t)rowB * lds + k0 + 4 * m);
        float* xb = Xd + m * XB + 4 * p;
        ulonglong2 t;
        t.x = dup2(a.x); t.y = dup2(b.x); *(ulonglong2*)(xb         ) = t;
        t.x = dup2(a.y); t.y = dup2(b.y); *(ulonglong2*)(xb + XJ    ) = t;
        t.x = dup2(a.z); t.y = dup2(b.z); *(ulonglong2*)(xb + 2 * XJ) = t;
        t.x = dup2(a.w); t.y = dup2(b.w); *(ulonglong2*)(xb + 3 * XJ) = t;
    }
}
__device__ __forceinline__ void mma_fp32(const float* Ws, const float* Xd,
        int cg, int rg, ull acc[8][4]) {
    const float* wp = Ws + cg * 4;
    const float* xp = Xd + rg * 16;
    #pragma unroll 1
    for (int m = 0; m < 16; m++) {
        const float* wk = wp + m * 512;
        const float* xk = xp + m * XB;
        #pragma unroll
        for (int j = 0; j < 4; j++) {
            ulonglong2 wA = *(const ulonglong2*)(wk + j * 128);
            ulonglong2 wB = *(const ulonglong2*)(wk + j * 128 + 64);
            const float* xj = xk + j * XJ;
            ulonglong2 x0 = *(const ulonglong2*)(xj);
            ulonglong2 x1 = *(const ulonglong2*)(xj + 4);
            ulonglong2 x2 = *(const ulonglong2*)(xj + 8);
            ulonglong2 x3 = *(const ulonglong2*)(xj + 12);
            #define ROWF(i, xv)                                                 \
                acc[i][0] = ffma2(xv, wA.x, acc[i][0]);                         \
                acc[i][1] = ffma2(xv, wA.y, acc[i][1]);                         \
                acc[i][2] = ffma2(xv, wB.x, acc[i][2]);                         \
                acc[i][3] = ffma2(xv, wB.y, acc[i][3]);
            ROWF(0, x0.x) ROWF(1, x0.y) ROWF(2, x1.x) ROWF(3, x1.y)
            ROWF(4, x2.x) ROWF(5, x2.y) ROWF(6, x3.x) ROWF(7, x3.y)
            #undef ROWF
        }
    }
}
__device__ __forceinline__ void acc_init(ull acc[8][4], const float* __restrict__ bp) {
    ull b0 = *(const ull*)(bp), b1 = *(const ull*)(bp + 2);
    ull b2 = *(const ull*)(bp + 4), b3 = *(const ull*)(bp + 6);
    #pragma unroll
    for (int r = 0; r < 8; r++) {
        acc[r][0] = b0; acc[r][1] = b1; acc[r][2] = b2; acc[r][3] = b3;
    }
}
__device__ __forceinline__ void store_rows(float* __restrict__ dst, int dstride,
        ull acc[8][4], int row0, int n, int cg, int rg) {
    const int c = cg * 8;
    #pragma unroll
    for (int r = 0; r < 8; r++) {
        int row = row0 + rg * 8 + r;
        if (row < n) {
            ulonglong2 p0, p1;
            p0.x = acc[r][0]; p0.y = acc[r][1];
            p1.x = acc[r][2]; p1.y = acc[r][3];
            *(ulonglong2*)(dst + (size_t)row * dstride + c) = p0;
            *(ulonglong2*)(dst + (size_t)row * dstride + c + 4) = p1;
        }
    }
}
__device__ __forceinline__ void resid_store(float* resid, ull acc[8][4],
        const float* __restrict__ xres, int row0, int n, int cg, int rg) {
    const int c = cg * 8;
    #pragma unroll
    for (int r = 0; r < 8; r++) {
        int rl = rg * 8 + r;
        int row = row0 + rl;
        if (row < n) {
            ulonglong2 x0 = *(const ulonglong2*)(xres + (size_t)row * DIM + c);
            ulonglong2 x1 = *(const ulonglong2*)(xres + (size_t)row * DIM + c + 4);
            ulonglong2 p0, p1;
            p0.x = add2(acc[r][0], x0.x); p0.y = add2(acc[r][1], x0.y);
            p1.x = add2(acc[r][2], x1.x); p1.y = add2(acc[r][3], x1.y);
            *(ulonglong2*)(resid + rl * DIM + c) = p0;
            *(ulonglong2*)(resid + rl * DIM + c + 4) = p1;
        }
    }
}
// LN over RT rows; emits fp32 + bf16 hi/lo split.
__device__ __forceinline__ void ln_rows_emit(const float* resid,
        const float* __restrict__ gam, const float* __restrict__ bet,
        int row0, int n, int tid) {
    const int wid = tid >> 5, lane = tid & 31;
    const int d = lane * 4;
    float4 gv = *(const float4*)(gam + d);
    float4 bv = *(const float4*)(bet + d);
    for (int rl = wid; rl < RT; rl += 8) {
        int row = row0 + rl;
        if (row >= n) continue;
        float4 v = *(const float4*)(resid + rl * DIM + d);
        float s  = v.x + v.y + v.z + v.w;
        float sq = v.x * v.x + v.y * v.y + v.z * v.z + v.w * v.w;
        #pragma unroll
        for (int m = 16; m; m >>= 1) {
            s  += __shfl_xor_sync(0xffffffffu, s,  m);
            sq += __shfl_xor_sync(0xffffffffu, sq, m);
        }
        float mu = s * (1.f / DIM);
        float var = sq * (1.f / DIM) - mu * mu;
        float rs = rsqrtf(var + 1e-5f);
        float4 o;
        o.x = (v.x - mu) * rs * gv.x + bv.x;
        o.y = (v.y - mu) * rs * gv.y + bv.y;
        o.z = (v.z - mu) * rs * gv.z + bv.z;
        o.w = (v.w - mu) * rs * gv.w + bv.w;
        *(float4*)&g_x1[(size_t)row * DIM + d] = o;
        float hx = bf_hi(o.x), hy = bf_hi(o.y), hz = bf_hi(o.z), hw = bf_hi(o.w);
        uint2 hh, ll;
        hh.x = pbf(o.x, o.y);             hh.y = pbf(o.z, o.w);
        ll.x = pbf(o.x - hx, o.y - hy);   ll.y = pbf(o.z - hz, o.w - hw);
        *(uint2*)((uint16_t*)g_x1h + (size_t)row * DIM + d) = hh;
        *(uint2*)((uint16_t*)g_x1l + (size_t)row * DIM + d) = ll;
    }
}

// ====================== Kernel: weight convert/split ======================
__global__ __launch_bounds__(256) void k_cvt(const float* __restrict__ W1,
                                             const float* __restrict__ W2) {
    int i = blockIdx.x * 256 + threadIdx.x;          // 65536 threads
    {   // W1 [128k, 512n] -> [512n, 128k]
        int nn = i >> 7, kk = i & 127;
        float v = W1[(size_t)kk * FFN + nn];
        float h = bf_hi(v);
        g_w1h[i] = __float2bfloat16(v);
        g_w1l[i] = __float2bfloat16(v - h);
    }
    {   // W2 [512k, 128n] -> [128n, 512k]
        int nn = i >> 9, kk = i & 511;
        float v = W2[(size_t)kk * DIM + nn];
        float h = bf_hi(v);
        g_w2h[i] = __float2bfloat16(v);
        g_w2l[i] = __float2bfloat16(v - h);
    }
}

// ====================== Kernel A: h = x @ W_in + b ========================
__global__ __launch_bounds__(TPB, 2) void k_win(const float* __restrict__ x,
        const float* __restrict__ W, const float* __restrict__ b, int n) {
    extern __shared__ float sm[];
    float* Ws = sm;
    float* Xd = sm + KPH * 128;
    const int tid = threadIdx.x;
    const int cg = tid & 15, rg = tid >> 4;
    const int row0 = blockIdx.x * RT;
    ull acc[8][4];
    acc_init(acc, b + cg * 8);
    #pragma unroll 1
    for (int ph = 0; ph < 2; ph++) {
        __syncthreads();
        stage_w(Ws, W, ph * KPH, DIM, 0, tid);
        stage_x(Xd, x, DIM, ph * KPH, row0, n, tid);
        __syncthreads();
        mma_fp32(Ws, Xd, cg, rg, acc);
    }
    store_rows(g_h, DIM, acc, row0, n, cg, rg);
}

// ====================== Kernel B1: concat GEMM ============================
__global__ __launch_bounds__(TPB, 2) void k_msg1(const void* __restrict__ eidx,
        const float* __restrict__ Wu, const float* __restrict__ bu, int n) {
    extern __shared__ float sm[];
    float* Ws = sm;
    float* Xd = sm + KPH * 128;
    int* srcb = (int*)(Xd + XD_FLOATS);
    int* flag = srcb + RT * KNN;
    const int tid = threadIdx.x;
    const int cg = tid & 15, rg = tid >> 4;
    const int row0 = blockIdx.x * RT;
    if (tid == 0) {
        const long long* p64 = (const long long*)eidx;
        int ok = 1;
        #pragma unroll
        for (int i = 0; i < 16; i++) {
            long long v = p64[i];
            if (v < 0 || v >= (long long)n) ok = 0;
        }
        *flag = ok;
    }
    __syncthreads();
    const int is64 = *flag;
    for (int i = tid; i < RT * KNN; i += TPB) {
        int r = i / KNN;
        int row = row0 + r;
        int s = 0;
        if (row < n) {
            size_t e = (size_t)row * KNN + (i - r * KNN);
            long long v = is64 ? ((const long long*)eidx)[e]
                               : (long long)((const int*)eidx)[e];
            s = (int)v;
            s = min(max(s, 0), n - 1);
        }
        srcb[i] = s;
    }
    ull acc[8][4];
    acc_init(acc, bu + cg * 8);
    #pragma unroll 1
    for (int ph = 0; ph < 2; ph++) {
        __syncthreads();
        stage_w(Ws, Wu, ph * KPH, DIM, 0, tid);
        stage_x(Xd, g_h, DIM, ph * KPH, row0, n, tid);
        __syncthreads();
        mma_fp32(Ws, Xd, cg, rg, acc);
    }
    #pragma unroll 1
    for (int ph = 0; ph < 2; ph++) {
        __syncthreads();
        stage_w(Ws, Wu, DIM + ph * KPH, DIM, 0, tid);
        {
            const int m  = tid & 15;
            const int rp = (tid >> 4) & 1;
            const int w  = tid >> 5;
            const int d0 = ph * KPH + 4 * m;
            #pragma unroll 1
            for (int it = 0; it < 4; it++) {
                int p = (((w << 2) + it) << 1) + rp;
                int rA = 2 * p, rB = rA + 1;
                int rowA = row0 + rA, rowB = row0 + rB;
                float4 mA = make_float4(-3.4e38f, -3.4e38f, -3.4e38f, -3.4e38f);
                float4 mB = mA;
                const int* sA = srcb + rA * KNN;
                const int* sB = srcb + rB * KNN;
                #pragma unroll
                for (int j = 0; j < KNN; j++) {
                    float4 g = *(const float4*)(g_h + (size_t)sA[j] * DIM + d0);
                    mA.x = fmaxf(mA.x, g.x); mA.y = fmaxf(mA.y, g.y);
                    mA.z = fmaxf(mA.z, g.z); mA.w = fmaxf(mA.w, g.w);
                }
                #pragma unroll
                for (int j = 0; j < KNN; j++) {
                    float4 g = *(const float4*)(g_h + (size_t)sB[j] * DIM + d0);
                    mB.x = fmaxf(mB.x, g.x); mB.y = fmaxf(mB.y, g.y);
                    mB.z = fmaxf(mB.z, g.z); mB.w = fmaxf(mB.w, g.w);
                }
                float4 oA = make_float4(0.f, 0.f, 0.f, 0.f), oB = oA;
                if (rowA < n) {
                    float4 a = *(const float4*)(g_h + (size_t)rowA * DIM + d0);
                    oA.x = mA.x - a.x; oA.y = mA.y - a.y;
                    oA.z = mA.z - a.z; oA.w = mA.w - a.w;
                }
                if (rowB < n) {
                    float4 a = *(const float4*)(g_h + (size_t)rowB * DIM + d0);
                    oB.x = mB.x - a.x; oB.y = mB.y - a.y;
                    oB.z = mB.z - a.z; oB.w = mB.w - a.w;
                }
                float* xb = Xd + m * XB + 4 * p;
                ulonglong2 t;
                t.x = dup2(oA.x); t.y = dup2(oB.x); *(ulonglong2*)(xb         ) = t;
                t.x = dup2(oA.y); t.y = dup2(oB.y); *(ulonglong2*)(xb + XJ    ) = t;
                t.x = dup2(oA.z); t.y = dup2(oB.z); *(ulonglong2*)(xb + 2 * XJ) = t;
                t.x = dup2(oA.w); t.y = dup2(oB.w); *(ulonglong2*)(xb + 3 * XJ) = t;
            }
        }
        __syncthreads();
        mma_fp32(Ws, Xd, cg, rg, acc);
    }
    store_rows(g_h2, DIM, acc, row0, n, cg, rg);
}

// ====================== Kernel B2: W_out + LN1 (+bf16 emit) ===============
__global__ __launch_bounds__(TPB, 2) void k_msg2(const float* __restrict__ x,
        const float* __restrict__ Wo, const float* __restrict__ bo,
        const float* __restrict__ g1, const float* __restrict__ b1, int n) {
    extern __shared__ float sm[];
    float* Ws = sm;
    float* Xd = sm + KPH * 128;
    const int tid = threadIdx.x;
    const int cg = tid & 15, rg = tid >> 4;
    const int row0 = blockIdx.x * RT;
    ull acc[8][4];
    acc_init(acc, bo + cg * 8);
    #pragma unroll 1
    for (int ph = 0; ph < 2; ph++) {
        __syncthreads();
        stage_w(Ws, Wo, ph * KPH, DIM, 0, tid);
        stage_x(Xd, g_h2, DIM, ph * KPH, row0, n, tid);
        __syncthreads();
        mma_fp32(Ws, Xd, cg, rg, acc);
    }
    __syncthreads();
    float* resid = sm;
    resid_store(resid, acc, x, row0, n, cg, rg);
    __syncthreads();
    ln_rows_emit(resid, g1, b1, row0, n, tid);
}

// ====================== bf16 HMMA machinery ===============================
// Stage a [128 rows x 128 k] bf16 tile into smem (row stride SA).
__device__ __forceinline__ void stage_t(__nv_bfloat16* dst,
        const __nv_bfloat16* __restrict__ src, int ldk, int k0,
        int row0, int nvalid, int tid) {
    #pragma unroll
    for (int p = 0; p < 8; p++) {
        int i = tid + p * TPB;             // 2048 16B-chunks
        int row = i >> 4, ch = i & 15;
        uint4 v = make_uint4(0u, 0u, 0u, 0u);
        int gr = row0 + row;
        if (gr < nvalid)
            v = *(const uint4*)(src + (size_t)gr * ldk + k0 + ch * 8);
        *(uint4*)(dst + row * SA + ch * 8) = v;
    }
}

// One 128x(64-wide warp slice)x128 product accumulated into C.
__device__ __forceinline__ void mma_tile(uint32_t sA, uint32_t sB,
        int lane, int mw, int nw, float C[2][8][4]) {
    uint32_t aB = sA + (uint32_t)(((mw + (lane & 15)) * SA + (lane >> 4) * 8) * 2);
    uint32_t bB = sB + (uint32_t)(((nw + ((lane >> 4) << 3) + (lane & 7)) * SA
                                   + (((lane >> 3) & 1) << 3)) * 2);
    #pragma unroll
    for (int k = 0; k < 8; k++) {
        uint32_t a0[4], a1[4];
        ldsm4(a0, aB + k * 32);
        ldsm4(a1, aB + 16 * SA * 2 + k * 32);
        #pragma unroll
        for (int nj = 0; nj < 4; nj++) {
            uint32_t b[4];
            ldsm4(b, bB + nj * (16 * SA * 2) + k * 32);
            mma_bf16(C[0][nj * 2],     a0, b[0], b[1]);
            mma_bf16(C[0][nj * 2 + 1], a0, b[2], b[3]);
            mma_bf16(C[1][nj * 2],     a1, b[0], b[1]);
            mma_bf16(C[1][nj * 2 + 1], a1, b[2], b[3]);
        }
    }
}

// ====================== Kernel C: ffn1 via HMMA ===========================
// t = gelu(x1 @ W1 + b1). CTA tile M=128 x N=128 (grid.y=4), K=128.
// Split bf16: D = Ah*Bh + Ah*Bl + Al*Bh.
#define FS_BYTES (4 * 128 * SA * 2)   // 139264

__global__ __launch_bounds__(TPB, 1) void k_ffn1(const float* __restrict__ b1, int n) {
    extern __shared__ __nv_bfloat16 smb[];
    __nv_bfloat16* Ah = smb;
    __nv_bfloat16* Al = smb + 128 * SA;
    __nv_bfloat16* Bh = smb + 2 * 128 * SA;
    __nv_bfloat16* Bl = smb + 3 * 128 * SA;
    const int tid = threadIdx.x, wid = tid >> 5, lane = tid & 31;
    const int row0 = blockIdx.x * RT;
    const int colbase = blockIdx.y * 128;
    stage_t(Ah, g_x1h, DIM, 0, row0, n, tid);
    stage_t(Al, g_x1l, DIM, 0, row0, n, tid);
    stage_t(Bh, g_w1h, DIM, 0, colbase, 1 << 30, tid);
    stage_t(Bl, g_w1l, DIM, 0, colbase, 1 << 30, tid);
    __syncthreads();
    const int mw = (wid >> 1) * 32, nw = (wid & 1) * 64;
    float C[2][8][4];
    #pragma unroll
    for (int a = 0; a < 2; a++)
        #pragma unroll
        for (int b = 0; b < 8; b++)
            #pragma unroll
            for (int c = 0; c < 4; c++) C[a][b][c] = 0.f;
    uint32_t sAh = s2u(Ah), sAl = s2u(Al), sBh = s2u(Bh), sBl = s2u(Bl);
    mma_tile(sAh, sBh, lane, mw, nw, C);
    mma_tile(sAh, sBl, lane, mw, nw, C);
    mma_tile(sAl, sBh, lane, mw, nw, C);
    // epilogue: bias + gelu + bf16 split
    const int rL = lane >> 2, cL = (lane & 3) * 2;
    #pragma unroll
    for (int ni = 0; ni < 8; ni++) {
        int c = colbase + nw + ni * 8 + cL;
        float bb0 = __ldg(b1 + c), bb1 = __ldg(b1 + c + 1);
        #pragma unroll
        for (int mi = 0; mi < 2; mi++) {
            #pragma unroll
            for (int h = 0; h < 2; h++) {
                int row = row0 + mw + mi * 16 + h * 8 + rL;
                if (row < n) {
                    float v0 = gelu_exact(C[mi][ni][h * 2]     + bb0);
                    float v1 = gelu_exact(C[mi][ni][h * 2 + 1] + bb1);
                    float h0 = bf_hi(v0), h1 = bf_hi(v1);
                    *(uint32_t*)((uint16_t*)g_th + (size_t)row * FFN + c) = pbf(v0, v1);
                    *(uint32_t*)((uint16_t*)g_tl + (size_t)row * FFN + c) =
                        pbf(v0 - h0, v1 - h1);
                }
            }
        }
    }
}

// ====================== Kernel D: ffn2 via HMMA ===========================
// f = t @ W2 + b2; out = LN2(x1 + f). M=128 x N=128, K=512 in 4 chunks.
__global__ __launch_bounds__(TPB, 1) void k_ffn2(const float* __restrict__ b2,
        const float* __restrict__ g2, const float* __restrict__ bl,
        float* __restrict__ out, int n) {
    extern __shared__ __nv_bfloat16 smb[];
    __nv_bfloat16* Ah = smb;
    __nv_bfloat16* Al = smb + 128 * SA;
    __nv_bfloat16* Bh = smb + 2 * 128 * SA;
    __nv_bfloat16* Bl = smb + 3 * 128 * SA;
    const int tid = threadIdx.x, wid = tid >> 5, lane = tid & 31;
    const int row0 = blockIdx.x * RT;
    const int mw = (wid >> 1) * 32, nw = (wid & 1) * 64;
    float C[2][8][4];
    #pragma unroll
    for (int a = 0; a < 2; a++)
        #pragma unroll
        for (int b = 0; b < 8; b++)
            #pragma unroll
            for (int c = 0; c < 4; c++) C[a][b][c] = 0.f;
    uint32_t sAh = s2u(Ah), sAl = s2u(Al), sBh = s2u(Bh), sBl = s2u(Bl);
    #pragma unroll 1
    for (int kc = 0; kc < 4; kc++) {
        __syncthreads();
        stage_t(Ah, g_th,  FFN, kc * 128, row0, n, tid);
        stage_t(Al, g_tl,  FFN, kc * 128, row0, n, tid);
        stage_t(Bh, g_w2h, FFN, kc * 128, 0, 1 << 30, tid);
        stage_t(Bl, g_w2l, FFN, kc * 128, 0, 1 << 30, tid);
        __syncthreads();
        mma_tile(sAh, sBh, lane, mw, nw, C);
        mma_tile(sAh, sBl, lane, mw, nw, C);
        mma_tile(sAl, sBh, lane, mw, nw, C);
    }
    __syncthreads();                 // MMA reads done; reuse smem as resid
    float* resid = (float*)smb;      // 128 x RSTR floats = 67.6KB < 136KB
    const int rL = lane >> 2, cL = (lane & 3) * 2;
    #pragma unroll
    for (int ni = 0; ni < 8; ni++) {
        int c = nw + ni * 8 + cL;
        float bb0 = __ldg(b2 + c), bb1 = __ldg(b2 + c + 1);
        #pragma unroll
        for (int mi = 0; mi < 2; mi++) {
            #pragma unroll
            for (int h = 0; h < 2; h++) {
                int rl = mw + mi * 16 + h * 8 + rL;
                resid[rl * RSTR + c    ] = C[mi][ni][h * 2]     + bb0;
                resid[rl * RSTR + c + 1] = C[mi][ni][h * 2 + 1] + bb1;
            }
        }
    }
    __syncthreads();
    {
        const int d = lane * 4;
        float4 gv = *(const float4*)(g2 + d);
        float4 bv = *(const float4*)(bl + d);
        for (int rl = wid; rl < RT; rl += 8) {
            int row = row0 + rl;
            if (row >= n) continue;
            float4 v = *(const float4*)(resid + rl * RSTR + d);
            float4 xv = *(const float4*)&g_x1[(size_t)row * DIM + d];
            v.x += xv.x; v.y += xv.y; v.z += xv.z; v.w += xv.w;
            float s  = v.x + v.y + v.z + v.w;
            float sq = v.x * v.x + v.y * v.y + v.z * v.z + v.w * v.w;
            #pragma unroll
            for (int m = 16; m; m >>= 1) {
                s  += __shfl_xor_sync(0xffffffffu, s,  m);
                sq += __shfl_xor_sync(0xffffffffu, sq, m);
            }
            float mu = s * (1.f / DIM);
            float var = sq * (1.f / DIM) - mu * mu;
            float rs = rsqrtf(var + 1e-5f);
            float4 o;
            o.x = (v.x - mu) * rs * gv.x + bv.x;
            o.y = (v.y - mu) * rs * gv.y + bv.y;
            o.z = (v.z - mu) * rs * gv.z + bv.z;
            o.w = (v.w - mu) * rs * gv.w + bv.w;
            *(float4*)&out[(size_t)row * DIM + d] = o;
        }
    }
}

// =====================================================================
extern "C" void kernel_launch(void* const* d_in, const int* in_sizes, int n_in,
                              void* d_out, int out_size) {
    const float* x    = (const float*)d_in[0];
    const void*  ei   = (const void*)d_in[1];
    const float* Winw = (const float*)d_in[2];
    const float* Winb = (const float*)d_in[3];
    const float* Wupw = (const float*)d_in[4];
    const float* Wupb = (const float*)d_in[5];
    const float* Wouw = (const float*)d_in[6];
    const float* Woub = (const float*)d_in[7];
    const float* ln1g = (const float*)d_in[8];
    const float* ln1b = (const float*)d_in[9];
    const float* ln2g = (const float*)d_in[10];
    const float* ln2b = (const float*)d_in[11];
    const float* f1w  = (const float*)d_in[12];
    const float* f1b  = (const float*)d_in[13];
    const float* f2w  = (const float*)d_in[14];
    const float* f2b  = (const float*)d_in[15];
    float* out = (float*)d_out;

    const int n = in_sizes[0] / DIM;

    const int SMEM_GEMM = (KPH * 128 + XD_FLOATS) * 4;
    const int SMEM_MSG1 = SMEM_GEMM + (RT * KNN + 1) * 4;

    cudaFuncSetAttribute(k_win,  cudaFuncAttributeMaxDynamicSharedMemorySize, SMEM_GEMM);
    cudaFuncSetAttribute(k_msg1, cudaFuncAttributeMaxDynamicSharedMemorySize, SMEM_MSG1);
    cudaFuncSetAttribute(k_msg2, cudaFuncAttributeMaxDynamicSharedMemorySize, SMEM_GEMM);
    cudaFuncSetAttribute(k_ffn1, cudaFuncAttributeMaxDynamicSharedMemorySize, FS_BYTES);
    cudaFuncSetAttribute(k_ffn2, cudaFuncAttributeMaxDynamicSharedMemorySize, FS_BYTES);

    const int nb = (n + RT - 1) / RT;
    dim3 gc(nb, 4);

    k_cvt <<<256, 256>>>(f1w, f2w);
    k_win <<<nb, TPB, SMEM_GEMM>>>(x, Winw, Winb, n);
    k_msg1<<<nb, TPB, SMEM_MSG1>>>(ei, Wupw, Wupb, n);
    k_msg2<<<nb, TPB, SMEM_GEMM>>>(x, Wouw, Woub, ln1g, ln1b, n);
    k_ffn1<<<gc, TPB, FS_BYTES>>>(f1b, n);
    k_ffn2<<<nb, TPB, FS_BYTES>>>(f2b, ln2g, ln2b, out, n);
}

// round 13
// speedup vs baseline: 1.6757x; 1.2589x over previous
#include <cuda_runtime.h>
#include <cuda_bf16.h>
#include <cstdint>
#include <math.h>

#define DIM 128
#define FFN 512
#define KNN 9
#define TPB 256
#define RT  128      // rows per CTA tile
#define NMAX 50000

#define SA 136       // bf16 smem tile row stride (128 + 8 pad, conflict-free ldmatrix)
#define RSTR 132     // resid smem row stride (floats)
#define FS_BYTES (4 * 128 * SA * 2)                    // 139264
#define MSG1_BYTES (FS_BYTES + (RT * KNN + 2) * 4)

// ====================== scalar helpers ====================================
__device__ __forceinline__ float gelu_exact(float v) {
    return 0.5f * v * (1.0f + erff(v * 0.70710678118654752f));
}
__device__ __forceinline__ uint32_t pbf(float a, float b) {
    uint16_t ua = __bfloat16_as_ushort(__float2bfloat16(a));
    uint16_t ub = __bfloat16_as_ushort(__float2bfloat16(b));
    return (uint32_t)ua | ((uint32_t)ub << 16);
}
__device__ __forceinline__ float bf_hi(float v) {
    return __bfloat162float(__float2bfloat16(v));
}

// ====================== HMMA (compute_100-safe) helpers ===================
__device__ __forceinline__ uint32_t s2u(const void* p) {
    uint32_t a;
    asm("{ .reg .u64 t; cvta.to.shared.u64 t, %1; cvt.u32.u64 %0, t; }"
        : "=r"(a) : "l"(p));
    return a;
}
__device__ __forceinline__ void ldsm4(uint32_t* r, uint32_t addr) {
    asm volatile("ldmatrix.sync.aligned.m8n8.x4.shared.b16 {%0,%1,%2,%3}, [%4];"
        : "=r"(r[0]), "=r"(r[1]), "=r"(r[2]), "=r"(r[3]) : "r"(addr));
}
__device__ __forceinline__ void mma_bf16(float* c, const uint32_t* a,
                                         uint32_t b0, uint32_t b1) {
    asm volatile(
        "mma.sync.aligned.m16n8k16.row.col.f32.bf16.bf16.f32 "
        "{%0,%1,%2,%3}, {%4,%5,%6,%7}, {%8,%9}, {%0,%1,%2,%3};"
        : "+f"(c[0]), "+f"(c[1]), "+f"(c[2]), "+f"(c[3])
        : "r"(a[0]), "r"(a[1]), "r"(a[2]), "r"(a[3]), "r"(b0), "r"(b1));
}

// ====================== scratch (no allocations anywhere) =================
__device__ float g_h [(size_t)NMAX * DIM];
__device__ float g_x1[(size_t)NMAX * DIM];
__device__ __align__(256) __nv_bfloat16 g_hh [(size_t)NMAX * DIM];
__device__ __align__(256) __nv_bfloat16 g_hl [(size_t)NMAX * DIM];
__device__ __align__(256) __nv_bfloat16 g_h2h[(size_t)NMAX * DIM];
__device__ __align__(256) __nv_bfloat16 g_h2l[(size_t)NMAX * DIM];
__device__ __align__(256) __nv_bfloat16 g_x1h[(size_t)NMAX * DIM];
__device__ __align__(256) __nv_bfloat16 g_x1l[(size_t)NMAX * DIM];
__device__ __align__(256) __nv_bfloat16 g_th [(size_t)NMAX * FFN];
__device__ __align__(256) __nv_bfloat16 g_tl [(size_t)NMAX * FFN];
__device__ __align__(256) __nv_bfloat16 g_wih[DIM * DIM], g_wil[DIM * DIM];   // W_in^T  [128n,128k]
__device__ __align__(256) __nv_bfloat16 g_wuh[DIM * 256], g_wul[DIM * 256];   // W_upd^T [128n,256k]
__device__ __align__(256) __nv_bfloat16 g_woh[DIM * DIM], g_wol[DIM * DIM];   // W_out^T [128n,128k]
__device__ __align__(256) __nv_bfloat16 g_w1h[FFN * DIM], g_w1l[FFN * DIM];   // ffn1^T  [512n,128k]
__device__ __align__(256) __nv_bfloat16 g_w2h[DIM * FFN], g_w2l[DIM * FFN];   // ffn2^T  [128n,512k]

// ====================== staging ===========================================
// bf16 src -> smem tile [128 rows x 128 k], row stride SA
__device__ __forceinline__ void stage_t(__nv_bfloat16* dst,
        const __nv_bfloat16* __restrict__ src, int ldk, int k0,
        int row0, int nvalid, int tid) {
    #pragma unroll
    for (int p = 0; p < 8; p++) {
        int i = tid + p * TPB;
        int row = i >> 4, ch = i & 15;
        uint4 v = make_uint4(0u, 0u, 0u, 0u);
        int gr = row0 + row;
        if (gr < nvalid)
            v = *(const uint4*)(src + (size_t)gr * ldk + k0 + ch * 8);
        *(uint4*)(dst + row * SA + ch * 8) = v;
    }
}

// fp32 src -> split hi/lo smem tiles
__device__ __forceinline__ void stage_s(__nv_bfloat16* Ah, __nv_bfloat16* Al,
        const float* __restrict__ src, int ldk, int k0,
        int row0, int nvalid, int tid) {
    #pragma unroll
    for (int p = 0; p < 8; p++) {
        int i = tid + p * TPB;
        int row = i >> 4, ch = i & 15;
        float4 v0 = make_float4(0.f, 0.f, 0.f, 0.f), v1 = v0;
        int gr = row0 + row;
        if (gr < nvalid) {
            const float* s = src + (size_t)gr * ldk + k0 + ch * 8;
            v0 = *(const float4*)s;
            v1 = *(const float4*)(s + 4);
        }
        uint4 hh, ll;
        hh.x = pbf(v0.x, v0.y); hh.y = pbf(v0.z, v0.w);
        hh.z = pbf(v1.x, v1.y); hh.w = pbf(v1.z, v1.w);
        ll.x = pbf(v0.x - bf_hi(v0.x), v0.y - bf_hi(v0.y));
        ll.y = pbf(v0.z - bf_hi(v0.z), v0.w - bf_hi(v0.w));
        ll.z = pbf(v1.x - bf_hi(v1.x), v1.y - bf_hi(v1.y));
        ll.w = pbf(v1.z - bf_hi(v1.z), v1.w - bf_hi(v1.w));
        *(uint4*)(Ah + row * SA + ch * 8) = hh;
        *(uint4*)(Al + row * SA + ch * 8) = ll;
    }
}

// ====================== core warp-tile MMA ================================
// One 128 x (64-wide warp slice) x 128 product accumulated into C.
__device__ __forceinline__ void mma_tile(uint32_t sA, uint32_t sB,
        int lane, int mw, int nw, float C[2][8][4]) {
    uint32_t aB = sA + (uint32_t)(((mw + (lane & 15)) * SA + (lane >> 4) * 8) * 2);
    uint32_t bB = sB + (uint32_t)(((nw + ((lane >> 4) << 3) + (lane & 7)) * SA
                                   + (((lane >> 3) & 1) << 3)) * 2);
    #pragma unroll
    for (int k = 0; k < 8; k++) {
        uint32_t a0[4], a1[4];
        ldsm4(a0, aB + k * 32);
        ldsm4(a1, aB + 16 * SA * 2 + k * 32);
        #pragma unroll
        for (int nj = 0; nj < 4; nj++) {
            uint32_t b[4];
            ldsm4(b, bB + nj * (16 * SA * 2) + k * 32);
            mma_bf16(C[0][nj * 2],     a0, b[0], b[1]);
            mma_bf16(C[0][nj * 2 + 1], a0, b[2], b[3]);
            mma_bf16(C[1][nj * 2],     a1, b[0], b[1]);
            mma_bf16(C[1][nj * 2 + 1], a1, b[2], b[3]);
        }
    }
}
#define C_ZERO(C)                                   \
    _Pragma("unroll")                               \
    for (int a_ = 0; a_ < 2; a_++)                  \
        _Pragma("unroll")                           \
        for (int b_ = 0; b_ < 8; b_++)              \
            _Pragma("unroll")                       \
            for (int c_ = 0; c_ < 4; c_++) C[a_][b_][c_] = 0.f;

// split product for one K-chunk: D += Ah*Bh + Ah*Bl + Al*Bh
__device__ __forceinline__ void mma_split(uint32_t sAh, uint32_t sAl,
        uint32_t sBh, uint32_t sBl, int lane, int mw, int nw, float C[2][8][4]) {
    mma_tile(sAh, sBh, lane, mw, nw, C);
    mma_tile(sAh, sBl, lane, mw, nw, C);
    mma_tile(sAl, sBh, lane, mw, nw, C);
}

// LN over RT rows of resid (stride rstr); emits fp32 + bf16 hi/lo split.
__device__ __forceinline__ void ln_rows_emit(const float* resid, int rstr,
        const float* __restrict__ gam, const float* __restrict__ bet,
        float* __restrict__ dstf, __nv_bfloat16* dsth, __nv_bfloat16* dstl,
        int row0, int n, int tid) {
    const int wid = tid >> 5, lane = tid & 31;
    const int d = lane * 4;
    float4 gv = *(const float4*)(gam + d);
    float4 bv = *(const float4*)(bet + d);
    for (int rl = wid; rl < RT; rl += 8) {
        int row = row0 + rl;
        if (row >= n) continue;
        float4 v = *(const float4*)(resid + rl * rstr + d);
        float s  = v.x + v.y + v.z + v.w;
        float sq = v.x * v.x + v.y * v.y + v.z * v.z + v.w * v.w;
        #pragma unroll
        for (int m = 16; m; m >>= 1) {
            s  += __shfl_xor_sync(0xffffffffu, s,  m);
            sq += __shfl_xor_sync(0xffffffffu, sq, m);
        }
        float mu = s * (1.f / DIM);
        float var = sq * (1.f / DIM) - mu * mu;
        float rs = rsqrtf(var + 1e-5f);
        float4 o;
        o.x = (v.x - mu) * rs * gv.x + bv.x;
        o.y = (v.y - mu) * rs * gv.y + bv.y;
        o.z = (v.z - mu) * rs * gv.z + bv.z;
        o.w = (v.w - mu) * rs * gv.w + bv.w;
        if (dstf) *(float4*)(dstf + (size_t)row * DIM + d) = o;
        uint2 hh, ll;
        hh.x = pbf(o.x, o.y);
        hh.y = pbf(o.z, o.w);
        ll.x = pbf(o.x - bf_hi(o.x), o.y - bf_hi(o.y));
        ll.y = pbf(o.z - bf_hi(o.z), o.w - bf_hi(o.w));
        *(uint2*)((uint16_t*)dsth + (size_t)row * DIM + d) = hh;
        *(uint2*)((uint16_t*)dstl + (size_t)row * DIM + d) = ll;
    }
}

// ====================== Kernel: weight convert/split ======================
__global__ __launch_bounds__(256) void k_cvt(const float* __restrict__ Wi,
        const float* __restrict__ Wu, const float* __restrict__ Wo,
        const float* __restrict__ W1, const float* __restrict__ W2) {
    int i = blockIdx.x * 256 + threadIdx.x;          // 65536 threads
    {   // ffn1 [128k,512n] -> [512n,128k]
        int nn = i >> 7, kk = i & 127;
        float v = W1[(size_t)kk * FFN + nn];
        g_w1h[i] = __float2bfloat16(v);
        g_w1l[i] = __float2bfloat16(v - bf_hi(v));
    }
    {   // ffn2 [512k,128n] -> [128n,512k]
        int nn = i >> 9, kk = i & 511;
        float v = W2[(size_t)kk * DIM + nn];
        g_w2h[i] = __float2bfloat16(v);
        g_w2l[i] = __float2bfloat16(v - bf_hi(v));
    }
    if (i < DIM * DIM) {    // W_in [128k,128n] -> [128n,128k]
        int nn = i >> 7, kk = i & 127;
        float v = Wi[(size_t)kk * DIM + nn];
        g_wih[i] = __float2bfloat16(v);
        g_wil[i] = __float2bfloat16(v - bf_hi(v));
    }
    if (i < DIM * DIM) {    // W_out
        int nn = i >> 7, kk = i & 127;
        float v = Wo[(size_t)kk * DIM + nn];
        g_woh[i] = __float2bfloat16(v);
        g_wol[i] = __float2bfloat16(v - bf_hi(v));
    }
    if (i < DIM * 256) {    // W_upd [256k,128n] -> [128n,256k]
        int kk = i >> 7, nn = i & 127;
        float v = Wu[(size_t)kk * DIM + nn];
        g_wuh[nn * 256 + kk] = __float2bfloat16(v);
        g_wul[nn * 256 + kk] = __float2bfloat16(v - bf_hi(v));
    }
}

// ====================== Kernel A: h = x @ W_in + b  (HMMA) ================
__global__ __launch_bounds__(TPB, 1) void k_win(const float* __restrict__ x,
        const float* __restrict__ b, int n) {
    extern __shared__ __nv_bfloat16 smb[];
    __nv_bfloat16* Ah = smb;
    __nv_bfloat16* Al = smb + 128 * SA;
    __nv_bfloat16* Bh = smb + 2 * 128 * SA;
    __nv_bfloat16* Bl = smb + 3 * 128 * SA;
    const int tid = threadIdx.x, wid = tid >> 5, lane = tid & 31;
    const int row0 = blockIdx.x * RT;
    stage_s(Ah, Al, x, DIM, 0, row0, n, tid);
    stage_t(Bh, g_wih, DIM, 0, 0, 1 << 30, tid);
    stage_t(Bl, g_wil, DIM, 0, 0, 1 << 30, tid);
    __syncthreads();
    const int mw = (wid >> 1) * 32, nw = (wid & 1) * 64;
    float C[2][8][4];
    C_ZERO(C)
    mma_split(s2u(Ah), s2u(Al), s2u(Bh), s2u(Bl), lane, mw, nw, C);
    const int rL = lane >> 2, cL = (lane & 3) * 2;
    #pragma unroll
    for (int ni = 0; ni < 8; ni++) {
        int c = nw + ni * 8 + cL;
        float bb0 = __ldg(b + c), bb1 = __ldg(b + c + 1);
        #pragma unroll
        for (int mi = 0; mi < 2; mi++) {
            #pragma unroll
            for (int h = 0; h < 2; h++) {
                int row = row0 + mw + mi * 16 + h * 8 + rL;
                if (row < n) {
                    float v0 = C[mi][ni][h * 2]     + bb0;
                    float v1 = C[mi][ni][h * 2 + 1] + bb1;
                    *(float2*)(g_h + (size_t)row * DIM + c) = make_float2(v0, v1);
                    *(uint32_t*)((uint16_t*)g_hh + (size_t)row * DIM + c) = pbf(v0, v1);
                    *(uint32_t*)((uint16_t*)g_hl + (size_t)row * DIM + c) =
                        pbf(v0 - bf_hi(v0), v1 - bf_hi(v1));
                }
            }
        }
    }
}

// ====================== Kernel B1: h2 = [h|md] @ W_upd + bu  (HMMA) =======
// K=256 as 2 chunks: chunk0 pre-split h; chunk1 gathers maxdiff in fp32
// and splits in-register. edge_index dtype auto-detected (int64/int32).
__global__ __launch_bounds__(TPB, 1) void k_msg1(const void* __restrict__ eidx,
        const float* __restrict__ bu, int n) {
    extern __shared__ __nv_bfloat16 smb[];
    __nv_bfloat16* Ah = smb;
    __nv_bfloat16* Al = smb + 128 * SA;
    __nv_bfloat16* Bh = smb + 2 * 128 * SA;
    __nv_bfloat16* Bl = smb + 3 * 128 * SA;
    int* srcb = (int*)(smb + 4 * 128 * SA);
    int* flag = srcb + RT * KNN;
    const int tid = threadIdx.x, wid = tid >> 5, lane = tid & 31;
    const int row0 = blockIdx.x * RT;
    if (tid == 0) {
        const long long* p64 = (const long long*)eidx;
        int ok = 1;
        #pragma unroll
        for (int i = 0; i < 16; i++) {
            long long v = p64[i];
            if (v < 0 || v >= (long long)n) ok = 0;
        }
        *flag = ok;
    }
    __syncthreads();
    const int is64 = *flag;
    for (int i = tid; i < RT * KNN; i += TPB) {
        int r = i / KNN;
        int row = row0 + r;
        int s = 0;
        if (row < n) {
            size_t e = (size_t)row * KNN + (i - r * KNN);
            long long v = is64 ? ((const long long*)eidx)[e]
                               : (long long)((const int*)eidx)[e];
            s = (int)v;
            s = min(max(s, 0), n - 1);
        }
        srcb[i] = s;
    }
    const int mw = (wid >> 1) * 32, nw = (wid & 1) * 64;
    float C[2][8][4];
    C_ZERO(C)
    uint32_t sAh = s2u(Ah), sAl = s2u(Al), sBh = s2u(Bh), sBl = s2u(Bl);
    // chunk 0: h half
    stage_t(Ah, g_hh, DIM, 0, row0, n, tid);
    stage_t(Al, g_hl, DIM, 0, row0, n, tid);
    stage_t(Bh, g_wuh, 256, 0, 0, 1 << 30, tid);
    stage_t(Bl, g_wul, 256, 0, 0, 1 << 30, tid);
    __syncthreads();
    mma_split(sAh, sAl, sBh, sBl, lane, mw, nw, C);
    __syncthreads();
    // chunk 1: maxdiff half (gather + split in-register)
    #pragma unroll 1
    for (int p = 0; p < 8; p++) {
        int i = tid + p * TPB;
        int r = i >> 4, ch = i & 15;
        int d0 = ch * 8;
        int row = row0 + r;
        float4 mA = make_float4(-3.4e38f, -3.4e38f, -3.4e38f, -3.4e38f);
        float4 mB = mA;
        const int* sp = srcb + r * KNN;
        #pragma unroll
        for (int j = 0; j < KNN; j++) {
            const float* hp = g_h + (size_t)sp[j] * DIM + d0;
            float4 a = *(const float4*)hp;
            float4 bq = *(const float4*)(hp + 4);
            mA.x = fmaxf(mA.x, a.x);  mA.y = fmaxf(mA.y, a.y);
            mA.z = fmaxf(mA.z, a.z);  mA.w = fmaxf(mA.w, a.w);
            mB.x = fmaxf(mB.x, bq.x); mB.y = fmaxf(mB.y, bq.y);
            mB.z = fmaxf(mB.z, bq.z); mB.w = fmaxf(mB.w, bq.w);
        }
        float4 o0 = make_float4(0.f, 0.f, 0.f, 0.f), o1 = o0;
        if (row < n) {
            const float* op = g_h + (size_t)row * DIM + d0;
            float4 a = *(const float4*)op;
            float4 bq = *(const float4*)(op + 4);
            o0.x = mA.x - a.x;  o0.y = mA.y - a.y;
            o0.z = mA.z - a.z;  o0.w = mA.w - a.w;
            o1.x = mB.x - bq.x; o1.y = mB.y - bq.y;
            o1.z = mB.z - bq.z; o1.w = mB.w - bq.w;
        }
        uint4 hh, ll;
        hh.x = pbf(o0.x, o0.y); hh.y = pbf(o0.z, o0.w);
        hh.z = pbf(o1.x, o1.y); hh.w = pbf(o1.z, o1.w);
        ll.x = pbf(o0.x - bf_hi(o0.x), o0.y - bf_hi(o0.y));
        ll.y = pbf(o0.z - bf_hi(o0.z), o0.w - bf_hi(o0.w));
        ll.z = pbf(o1.x - bf_hi(o1.x), o1.y - bf_hi(o1.y));
        ll.w = pbf(o1.z - bf_hi(o1.z), o1.w - bf_hi(o1.w));
        *(uint4*)(Ah + r * SA + ch * 8) = hh;
        *(uint4*)(Al + r * SA + ch * 8) = ll;
    }
    stage_t(Bh, g_wuh, 256, 128, 0, 1 << 30, tid);
    stage_t(Bl, g_wul, 256, 128, 0, 1 << 30, tid);
    __syncthreads();
    mma_split(sAh, sAl, sBh, sBl, lane, mw, nw, C);
    // epilogue: + bu, split to g_h2h/l
    const int rL = lane >> 2, cL = (lane & 3) * 2;
    #pragma unroll
    for (int ni = 0; ni < 8; ni++) {
        int c = nw + ni * 8 + cL;
        float bb0 = __ldg(bu + c), bb1 = __ldg(bu + c + 1);
        #pragma unroll
        for (int mi = 0; mi < 2; mi++) {
            #pragma unroll
            for (int h = 0; h < 2; h++) {
                int row = row0 + mw + mi * 16 + h * 8 + rL;
                if (row < n) {
                    float v0 = C[mi][ni][h * 2]     + bb0;
                    float v1 = C[mi][ni][h * 2 + 1] + bb1;
                    *(uint32_t*)((uint16_t*)g_h2h + (size_t)row * DIM + c) = pbf(v0, v1);
                    *(uint32_t*)((uint16_t*)g_h2l + (size_t)row * DIM + c) =
                        pbf(v0 - bf_hi(v0), v1 - bf_hi(v1));
                }
            }
        }
    }
}

// ====================== Kernel B2: W_out + LN1  (HMMA) ====================
__global__ __launch_bounds__(TPB, 1) void k_msg2(const float* __restrict__ x,
        const float* __restrict__ bo, const float* __restrict__ g1,
        const float* __restrict__ b1, int n) {
    extern __shared__ __nv_bfloat16 smb[];
    __nv_bfloat16* Ah = smb;
    __nv_bfloat16* Al = smb + 128 * SA;
    __nv_bfloat16* Bh = smb + 2 * 128 * SA;
    __nv_bfloat16* Bl = smb + 3 * 128 * SA;
    const int tid = threadIdx.x, wid = tid >> 5, lane = tid & 31;
    const int row0 = blockIdx.x * RT;
    stage_t(Ah, g_h2h, DIM, 0, row0, n, tid);
    stage_t(Al, g_h2l, DIM, 0, row0, n, tid);
    stage_t(Bh, g_woh, DIM, 0, 0, 1 << 30, tid);
    stage_t(Bl, g_wol, DIM, 0, 0, 1 << 30, tid);
    __syncthreads();
    const int mw = (wid >> 1) * 32, nw = (wid & 1) * 64;
    float C[2][8][4];
    C_ZERO(C)
    mma_split(s2u(Ah), s2u(Al), s2u(Bh), s2u(Bl), lane, mw, nw, C);
    __syncthreads();                 // MMA reads done; reuse smem as resid
    float* resid = (float*)smb;      // 128 x RSTR floats
    const int rL = lane >> 2, cL = (lane & 3) * 2;
    #pragma unroll
    for (int ni = 0; ni < 8; ni++) {
        int c = nw + ni * 8 + cL;
        float bb0 = __ldg(bo + c), bb1 = __ldg(bo + c + 1);
        #pragma unroll
        for (int mi = 0; mi < 2; mi++) {
            #pragma unroll
            for (int h = 0; h < 2; h++) {
                int rl = mw + mi * 16 + h * 8 + rL;
                int row = row0 + rl;
                float2 xv = make_float2(0.f, 0.f);
                if (row < n) xv = *(const float2*)(x + (size_t)row * DIM + c);
                resid[rl * RSTR + c    ] = C[mi][ni][h * 2]     + bb0 + xv.x;
                resid[rl * RSTR + c + 1] = C[mi][ni][h * 2 + 1] + bb1 + xv.y;
            }
        }
    }
    __syncthreads();
    ln_rows_emit(resid, RSTR, g1, b1, g_x1, g_x1h, g_x1l, row0, n, tid);
}

// ====================== Kernel C: ffn1 (HMMA, proven) =====================
__global__ __launch_bounds__(TPB, 1) void k_ffn1(const float* __restrict__ b1, int n) {
    extern __shared__ __nv_bfloat16 smb[];
    __nv_bfloat16* Ah = smb;
    __nv_bfloat16* Al = smb + 128 * SA;
    __nv_bfloat16* Bh = smb + 2 * 128 * SA;
    __nv_bfloat16* Bl = smb + 3 * 128 * SA;
    const int tid = threadIdx.x, wid = tid >> 5, lane = tid & 31;
    const int row0 = blockIdx.x * RT;
    const int colbase = blockIdx.y * 128;
    stage_t(Ah, g_x1h, DIM, 0, row0, n, tid);
    stage_t(Al, g_x1l, DIM, 0, row0, n, tid);
    stage_t(Bh, g_w1h, DIM, 0, colbase, 1 << 30, tid);
    stage_t(Bl, g_w1l, DIM, 0, colbase, 1 << 30, tid);
    __syncthreads();
    const int mw = (wid >> 1) * 32, nw = (wid & 1) * 64;
    float C[2][8][4];
    C_ZERO(C)
    mma_split(s2u(Ah), s2u(Al), s2u(Bh), s2u(Bl), lane, mw, nw, C);
    const int rL = lane >> 2, cL = (lane & 3) * 2;
    #pragma unroll
    for (int ni = 0; ni < 8; ni++) {
        int c = colbase + nw + ni * 8 + cL;
        float bb0 = __ldg(b1 + c), bb1 = __ldg(b1 + c + 1);
        #pragma unroll
        for (int mi = 0; mi < 2; mi++) {
            #pragma unroll
            for (int h = 0; h < 2; h++) {
                int row = row0 + mw + mi * 16 + h * 8 + rL;
                if (row < n) {
                    float v0 = gelu_exact(C[mi][ni][h * 2]     + bb0);
                    float v1 = gelu_exact(C[mi][ni][h * 2 + 1] + bb1);
                    *(uint32_t*)((uint16_t*)g_th + (size_t)row * FFN + c) = pbf(v0, v1);
                    *(uint32_t*)((uint16_t*)g_tl + (size_t)row * FFN + c) =
                        pbf(v0 - bf_hi(v0), v1 - bf_hi(v1));
                }
            }
        }
    }
}

// ====================== Kernel D: ffn2 + LN2 (HMMA, proven) ===============
__global__ __launch_bounds__(TPB, 1) void k_ffn2(const float* __restrict__ b2,
        const float* __restrict__ g2, const float* __restrict__ bl,
        float* __restrict__ out, int n) {
    extern __shared__ __nv_bfloat16 smb[];
    __nv_bfloat16* Ah = smb;
    __nv_bfloat16* Al = smb + 128 * SA;
    __nv_bfloat16* Bh = smb + 2 * 128 * SA;
    __nv_bfloat16* Bl = smb + 3 * 128 * SA;
    const int tid = threadIdx.x, wid = tid >> 5, lane = tid & 31;
    const int row0 = blockIdx.x * RT;
    const int mw = (wid >> 1) * 32, nw = (wid & 1) * 64;
    float C[2][8][4];
    C_ZERO(C)
    uint32_t sAh = s2u(Ah), sAl = s2u(Al), sBh = s2u(Bh), sBl = s2u(Bl);
    #pragma unroll 1
    for (int kc = 0; kc < 4; kc++) {
        __syncthreads();
        stage_t(Ah, g_th,  FFN, kc * 128, row0, n, tid);
        stage_t(Al, g_tl,  FFN, kc * 128, row0, n, tid);
        stage_t(Bh, g_w2h, FFN, kc * 128, 0, 1 << 30, tid);
        stage_t(Bl, g_w2l, FFN, kc * 128, 0, 1 << 30, tid);
        __syncthreads();
        mma_split(sAh, sAl, sBh, sBl, lane, mw, nw, C);
    }
    __syncthreads();
    float* resid = (float*)smb;
    const int rL = lane >> 2, cL = (lane & 3) * 2;
    #pragma unroll
    for (int ni = 0; ni < 8; ni++) {
        int c = nw + ni * 8 + cL;
        float bb0 = __ldg(b2 + c), bb1 = __ldg(b2 + c + 1);
        #pragma unroll
        for (int mi = 0; mi < 2; mi++) {
            #pragma unroll
            for (int h = 0; h < 2; h++) {
                int rl = mw + mi * 16 + h * 8 + rL;
                int row = row0 + rl;
                float2 xv = make_float2(0.f, 0.f);
                if (row < n) xv = *(const float2*)(g_x1 + (size_t)row * DIM + c);
                resid[rl * RSTR + c    ] = C[mi][ni][h * 2]     + bb0 + xv.x;
                resid[rl * RSTR + c + 1] = C[mi][ni][h * 2 + 1] + bb1 + xv.y;
            }
        }
    }
    __syncthreads();
    {
        const int d = lane * 4;
        float4 gv = *(const float4*)(g2 + d);
        float4 bv = *(const float4*)(bl + d);
        for (int rl = wid; rl < RT; rl += 8) {
            int row = row0 + rl;
            if (row >= n) continue;
            float4 v = *(const float4*)(resid + rl * RSTR + d);
            float s  = v.x + v.y + v.z + v.w;
            float sq = v.x * v.x + v.y * v.y + v.z * v.z + v.w * v.w;
            #pragma unroll
            for (int m = 16; m; m >>= 1) {
                s  += __shfl_xor_sync(0xffffffffu, s,  m);
                sq += __shfl_xor_sync(0xffffffffu, sq, m);
            }
            float mu = s * (1.f / DIM);
            float var = sq * (1.f / DIM) - mu * mu;
            float rs = rsqrtf(var + 1e-5f);
            float4 o;
            o.x = (v.x - mu) * rs * gv.x + bv.x;
            o.y = (v.y - mu) * rs * gv.y + bv.y;
            o.z = (v.z - mu) * rs * gv.z + bv.z;
            o.w = (v.w - mu) * rs * gv.w + bv.w;
            *(float4*)&out[(size_t)row * DIM + d] = o;
        }
    }
}

// =====================================================================
extern "C" void kernel_launch(void* const* d_in, const int* in_sizes, int n_in,
                              void* d_out, int out_size) {
    const float* x    = (const float*)d_in[0];
    const void*  ei   = (const void*)d_in[1];
    const float* Winw = (const float*)d_in[2];
    const float* Winb = (const float*)d_in[3];
    const float* Wupw = (const float*)d_in[4];
    const float* Wupb = (const float*)d_in[5];
    const float* Wouw = (const float*)d_in[6];
    const float* Woub = (const float*)d_in[7];
    const float* ln1g = (const float*)d_in[8];
    const float* ln1b = (const float*)d_in[9];
    const float* ln2g = (const float*)d_in[10];
    const float* ln2b = (const float*)d_in[11];
    const float* f1w  = (const float*)d_in[12];
    const float* f1b  = (const float*)d_in[13];
    const float* f2w  = (const float*)d_in[14];
    const float* f2b  = (const float*)d_in[15];
    float* out = (float*)d_out;

    const int n = in_sizes[0] / DIM;

    cudaFuncSetAttribute(k_win,  cudaFuncAttributeMaxDynamicSharedMemorySize, FS_BYTES);
    cudaFuncSetAttribute(k_msg1, cudaFuncAttributeMaxDynamicSharedMemorySize, MSG1_BYTES);
    cudaFuncSetAttribute(k_msg2, cudaFuncAttributeMaxDynamicSharedMemorySize, FS_BYTES);
    cudaFuncSetAttribute(k_ffn1, cudaFuncAttributeMaxDynamicSharedMemorySize, FS_BYTES);
    cudaFuncSetAttribute(k_ffn2, cudaFuncAttributeMaxDynamicSharedMemorySize, FS_BYTES);

    const int nb = (n + RT - 1) / RT;
    dim3 gc(nb, 4);

    k_cvt <<<256, 256>>>(Winw, Wupw, Wouw, f1w, f2w);
    k_win <<<nb, TPB, FS_BYTES>>>(x, Winb, n);
    k_msg1<<<nb, TPB, MSG1_BYTES>>>(ei, Wupb, n);
    k_msg2<<<nb, TPB, FS_BYTES>>>(x, Woub, ln1g, ln1b, n);
    k_ffn1<<<gc, TPB, FS_BYTES>>>(f1b, n);
    k_ffn2<<<nb, TPB, FS_BYTES>>>(f2b, ln2g, ln2b, out, n);
}